// round 8
// baseline (speedup 1.0000x reference)
#include <cuda_runtime.h>
#include <cuda_bf16.h>
#include <math.h>

// Problem constants (fixed shapes for RoIPointPool3d_23845658427905)
#define BB   4
#define NPTS 16384
#define MM   128
#define CF   128
#define SS   512
#define OUTF (3 + CF)   // 131 floats per pooled row
#define BPC  4          // boxes per mask CTA
#define PSPL 4          // point-range splits per box group
#define PPS  (NPTS / PSPL)   // 4096 points per split
#define STG_ROWS 64          // rows per gather stage (8 stages of 64)
#define STG_F    (STG_ROWS * OUTF)      // 8384 floats per stage
#define STG_F4   (STG_F / 4)            // 2096 float4 per stage

// Scratch (device globals — no allocation allowed)
__device__ int g_table[BB * MM * PSPL * SS]; // per (box, split): ordered in-box indices
__device__ int g_cnt[BB * MM * PSPL];        // per (box, split): in-box counts

// ---------------------------------------------------------------------------
// Kernel 1: fused box-prep (fp64 sincos, fast-math immune) + membership +
// ordered compaction. (R5 version — proven, no cull.)
// ---------------------------------------------------------------------------
__global__ __launch_bounds__(512) void roipool_mask_kernel(
    const float* __restrict__ points,   // (B, N, 3)
    const float* __restrict__ boxes)    // (B, M, 7)
{
    const int split = blockIdx.x & (PSPL - 1);
    const int quad  = blockIdx.x >> 2;       // 0..127
    const int bm0   = quad * BPC;            // first box of the quad
    const int b     = bm0 >> 7;              // / MM

    __shared__ float    sprep[BPC * 8];      // cx, cy, czc, hx, hy, hz, ca, sa
    __shared__ unsigned sball[BPC][16][8];
    __shared__ int      wtot[BPC][16];

    const int tid  = threadIdx.x;
    const int lane = tid & 31;
    const int w    = tid >> 5;

    if (w == 0 && lane < BPC) {
        const int q = lane;
        const float* bx = boxes + (size_t)(bm0 + q) * 7;
        const float r0 = bx[0], r1 = bx[1], r2 = bx[2];
        const float r3 = bx[3], r4 = bx[4], r5 = bx[5], r6 = bx[6];
        double sv, cv;
        sincos(-(double)r6, &sv, &cv);
        float* o = sprep + q * 8;
        o[0] = r0;
        o[1] = r1;
        o[2] = __fadd_rn(r2, __fmul_rn(0.5f, r5));
        o[3] = __fmul_rn(0.5f, r3);
        o[4] = __fmul_rn(0.5f, r4);
        o[5] = __fmul_rn(0.5f, r5);
        o[6] = (float)cv;
        o[7] = (float)sv;
    }
    __syncthreads();

    float cx[BPC], cy[BPC], cz[BPC], hx[BPC], hy[BPC], hz[BPC], ca[BPC], sa[BPC];
    #pragma unroll
    for (int q = 0; q < BPC; q++) {
        cx[q] = sprep[q * 8 + 0]; cy[q] = sprep[q * 8 + 1];
        cz[q] = sprep[q * 8 + 2]; hx[q] = sprep[q * 8 + 3];
        hy[q] = sprep[q * 8 + 4]; hz[q] = sprep[q * 8 + 5];
        ca[q] = sprep[q * 8 + 6]; sa[q] = sprep[q * 8 + 7];
    }

    const int base_local = split * PPS + w * 256;          // batch-relative
    const float* pb = points + ((size_t)b * NPTS + base_local) * 3;

    int cnt[BPC];
    #pragma unroll
    for (int q = 0; q < BPC; q++) cnt[q] = 0;

    for (int j = 0; j < 8; j++) {
        const int i3 = (j * 32 + lane) * 3;
        const float x = pb[i3 + 0];
        const float y = pb[i3 + 1];
        const float z = pb[i3 + 2];
        #pragma unroll
        for (int q = 0; q < BPC; q++) {
            const float sx = __fsub_rn(x, cx[q]);
            const float sy = __fsub_rn(y, cy[q]);
            const float lx = __fsub_rn(__fmul_rn(sx, ca[q]), __fmul_rn(sy, sa[q]));
            const float ly = __fadd_rn(__fmul_rn(sx, sa[q]), __fmul_rn(sy, ca[q]));
            const float zd = __fsub_rn(z, cz[q]);
            const bool m = (fabsf(zd) <= hz[q]) && (fabsf(lx) < hx[q]) && (fabsf(ly) < hy[q]);
            const unsigned ball = __ballot_sync(0xffffffffu, m);
            if (lane == 0) sball[q][w][j] = ball;
            cnt[q] += __popc(ball);
        }
    }
    if (lane == 0) {
        #pragma unroll
        for (int q = 0; q < BPC; q++) wtot[q][w] = cnt[q];
    }
    __syncthreads();

    const unsigned lt = (1u << lane) - 1u;
    #pragma unroll
    for (int q = 0; q < BPC; q++) {
        int run = 0;
        #pragma unroll
        for (int v = 0; v < 16; v++)
            if (v < w) run += wtot[q][v];
        int* tbl = g_table + (size_t)((bm0 + q) * PSPL + split) * SS;
        #pragma unroll
        for (int j = 0; j < 8; j++) {
            const unsigned ball = sball[q][w][j];
            const int pre = __popc(ball & lt);
            if (((ball >> lane) & 1u) && (run + pre) < SS)
                tbl[run + pre] = base_local + j * 32 + lane;
            run += __popc(ball);
        }
    }

    if (tid < BPC) {
        int tot = 0;
        #pragma unroll
        for (int v = 0; v < 16; v++) tot += wtot[tid][v];
        g_cnt[(bm0 + tid) * PSPL + split] = tot;
    }
}

// ---------------------------------------------------------------------------
// Kernel 2: gather — double-buffered smem stage, conflict-free fill,
// flat coalesced drain. One CTA per box, 512 threads (16 warps).
// Fill (warp w -> stage rows 4w..4w+3): 4 aligned scalar feature segments
// (lane-stride 4B -> 1 L1 wavefront each, mostly L1 hits since the ~cnt
// unique rows repeat) + point prefix; STS at srow[3+lane+32k] (stride 4B ->
// conflict-free, 1 crossbar pass each). Drain: flat float4 stream
// LDS.128 + STG.128 -> ~1 global store wavefront per row instead of ~9.
// fill(st+1) and drain(st) sit between the same barrier pair for overlap.
// ---------------------------------------------------------------------------
__global__ __launch_bounds__(512) void roipool_gather_kernel(
    const float* __restrict__ points,   // (B, N, 3)
    const float* __restrict__ feats,    // (B, N, C)
    float* __restrict__ out,            // (B, M, S, 131)
    float* __restrict__ flags)          // (B, M)
{
    const int bm = blockIdx.x;
    const int b  = bm >> 7;             // / MM
    const int tid  = threadIdx.x;
    const int lane = tid & 31;
    const int w    = tid >> 5;          // 0..15

    __shared__ __align__(16) float sstage[2][STG_F];   // 2 x 33.5 KB
    __shared__ int sidx[SS];
    __shared__ int pf[4];
    __shared__ int scnt;

    if (tid == 0) {
        const int c0 = g_cnt[bm * PSPL + 0];
        const int c1 = g_cnt[bm * PSPL + 1];
        const int c2 = g_cnt[bm * PSPL + 2];
        const int c3 = g_cnt[bm * PSPL + 3];
        pf[0] = 0; pf[1] = c0; pf[2] = c0 + c1; pf[3] = c0 + c1 + c2;
        const int tot = c0 + c1 + c2 + c3;
        scnt = tot;
        flags[bm] = (tot == 0) ? 1.0f : 0.0f;
    }
    __syncthreads();
    const int cnt = scnt;

    float* obox = out + (size_t)bm * SS * OUTF;

    if (cnt == 0) {
        const float4 zz = make_float4(0.f, 0.f, 0.f, 0.f);
        float4* o4 = (float4*)obox;
        for (int i = tid; i < SS * OUTF / 4; i += 512) o4[i] = zz;
        return;
    }

    // resolve wrap-around index for this thread's row
    {
        const int s = tid;                       // SS == blockDim.x
        const int j = s % cnt;
        const int p = (j >= pf[3]) ? 3 : (j >= pf[2]) ? 2 : (j >= pf[1]) ? 1 : 0;
        sidx[s] = g_table[(size_t)(bm * PSPL + p) * SS + (j - pf[p])];
    }
    __syncthreads();

    const float* pbat = points + (size_t)b * NPTS * 3;
    const float* fbat = feats  + (size_t)b * NPTS * CF;

    // fill stage `st` into buffer st&1 (warp w -> stage rows 4w..4w+3)
    auto fill_stage = [&](int st) {
        float* sbuf = sstage[st & 1];
        float vv[4][4];
        float pv[4];
        #pragma unroll
        for (int r = 0; r < 4; r++) {
            const int idx = sidx[st * STG_ROWS + w * 4 + r];
            const float* frow = fbat + (size_t)idx * CF;
            vv[r][0] = frow[lane];
            vv[r][1] = frow[lane + 32];
            vv[r][2] = frow[lane + 64];
            vv[r][3] = frow[lane + 96];
            pv[r] = (lane < 3) ? pbat[(size_t)idx * 3 + lane] : 0.0f;
        }
        #pragma unroll
        for (int r = 0; r < 4; r++) {
            float* srow = sbuf + (w * 4 + r) * OUTF;
            srow[3 + lane]      = vv[r][0];
            srow[3 + lane + 32] = vv[r][1];
            srow[3 + lane + 64] = vv[r][2];
            srow[3 + lane + 96] = vv[r][3];
            if (lane < 3) srow[lane] = pv[r];
        }
    };

    fill_stage(0);
    __syncthreads();

    for (int st = 0; st < SS / STG_ROWS; st++) {
        if (st + 1 < SS / STG_ROWS) fill_stage(st + 1);
        // drain stage st: flat, perfectly coalesced float4 stream
        {
            const float4* s4 = (const float4*)sstage[st & 1];
            float4* d4 = (float4*)(obox + (size_t)st * STG_F);
            #pragma unroll
            for (int i = 0; i < (STG_F4 + 511) / 512; i++) {
                const int k = i * 512 + tid;
                if (k < STG_F4) d4[k] = s4[k];
            }
        }
        __syncthreads();
    }
}

// ---------------------------------------------------------------------------
extern "C" void kernel_launch(void* const* d_in, const int* in_sizes, int n_in,
                              void* d_out, int out_size)
{
    const float* points = (const float*)d_in[0];   // (B, N, 3)
    const float* feats  = (const float*)d_in[1];   // (B, N, C)
    const float* boxes  = (const float*)d_in[2];   // (B, M, 7)

    float* out   = (float*)d_out;
    float* flags = out + (size_t)BB * MM * SS * OUTF;  // empty flags appended

    roipool_mask_kernel<<<(BB * MM / BPC) * PSPL, 512>>>(points, boxes);
    roipool_gather_kernel<<<BB * MM, 512>>>(points, feats, out, flags);
}

// round 9
// speedup vs baseline: 1.0964x; 1.0964x over previous
#include <cuda_runtime.h>
#include <cuda_bf16.h>
#include <math.h>

// Problem constants (fixed shapes for RoIPointPool3d_23845658427905)
#define BB   4
#define NPTS 16384
#define MM   128
#define CF   128
#define SS   512
#define OUTF (3 + CF)   // 131 floats per pooled row
#define BPC  4          // boxes per mask CTA
#define PSPL 4          // point-range splits per box group
#define PPS  (NPTS / PSPL)   // 4096 points per split

// Scratch (device globals — no allocation allowed)
__device__ int g_table[BB * MM * PSPL * SS]; // per (box, split): ordered in-box indices
__device__ int g_cnt[BB * MM * PSPL];        // per (box, split): in-box counts

// ---------------------------------------------------------------------------
// Kernel 1: fused box-prep (fp64 sincos, fast-math immune) + membership +
// ordered compaction. (Proven R5 version — unchanged.)
// ---------------------------------------------------------------------------
__global__ __launch_bounds__(512) void roipool_mask_kernel(
    const float* __restrict__ points,   // (B, N, 3)
    const float* __restrict__ boxes)    // (B, M, 7)
{
    const int split = blockIdx.x & (PSPL - 1);
    const int quad  = blockIdx.x >> 2;       // 0..127
    const int bm0   = quad * BPC;            // first box of the quad
    const int b     = bm0 >> 7;              // / MM

    __shared__ float    sprep[BPC * 8];      // cx, cy, czc, hx, hy, hz, ca, sa
    __shared__ unsigned sball[BPC][16][8];
    __shared__ int      wtot[BPC][16];

    const int tid  = threadIdx.x;
    const int lane = tid & 31;
    const int w    = tid >> 5;

    if (w == 0 && lane < BPC) {
        const int q = lane;
        const float* bx = boxes + (size_t)(bm0 + q) * 7;
        const float r0 = bx[0], r1 = bx[1], r2 = bx[2];
        const float r3 = bx[3], r4 = bx[4], r5 = bx[5], r6 = bx[6];
        double sv, cv;
        sincos(-(double)r6, &sv, &cv);
        float* o = sprep + q * 8;
        o[0] = r0;
        o[1] = r1;
        o[2] = __fadd_rn(r2, __fmul_rn(0.5f, r5));
        o[3] = __fmul_rn(0.5f, r3);
        o[4] = __fmul_rn(0.5f, r4);
        o[5] = __fmul_rn(0.5f, r5);
        o[6] = (float)cv;
        o[7] = (float)sv;
    }
    __syncthreads();

    float cx[BPC], cy[BPC], cz[BPC], hx[BPC], hy[BPC], hz[BPC], ca[BPC], sa[BPC];
    #pragma unroll
    for (int q = 0; q < BPC; q++) {
        cx[q] = sprep[q * 8 + 0]; cy[q] = sprep[q * 8 + 1];
        cz[q] = sprep[q * 8 + 2]; hx[q] = sprep[q * 8 + 3];
        hy[q] = sprep[q * 8 + 4]; hz[q] = sprep[q * 8 + 5];
        ca[q] = sprep[q * 8 + 6]; sa[q] = sprep[q * 8 + 7];
    }

    const int base_local = split * PPS + w * 256;          // batch-relative
    const float* pb = points + ((size_t)b * NPTS + base_local) * 3;

    int cnt[BPC];
    #pragma unroll
    for (int q = 0; q < BPC; q++) cnt[q] = 0;

    for (int j = 0; j < 8; j++) {
        const int i3 = (j * 32 + lane) * 3;
        const float x = pb[i3 + 0];
        const float y = pb[i3 + 1];
        const float z = pb[i3 + 2];
        #pragma unroll
        for (int q = 0; q < BPC; q++) {
            const float sx = __fsub_rn(x, cx[q]);
            const float sy = __fsub_rn(y, cy[q]);
            const float lx = __fsub_rn(__fmul_rn(sx, ca[q]), __fmul_rn(sy, sa[q]));
            const float ly = __fadd_rn(__fmul_rn(sx, sa[q]), __fmul_rn(sy, ca[q]));
            const float zd = __fsub_rn(z, cz[q]);
            const bool m = (fabsf(zd) <= hz[q]) && (fabsf(lx) < hx[q]) && (fabsf(ly) < hy[q]);
            const unsigned ball = __ballot_sync(0xffffffffu, m);
            if (lane == 0) sball[q][w][j] = ball;
            cnt[q] += __popc(ball);
        }
    }
    if (lane == 0) {
        #pragma unroll
        for (int q = 0; q < BPC; q++) wtot[q][w] = cnt[q];
    }
    __syncthreads();

    const unsigned lt = (1u << lane) - 1u;
    #pragma unroll
    for (int q = 0; q < BPC; q++) {
        int run = 0;
        #pragma unroll
        for (int v = 0; v < 16; v++)
            if (v < w) run += wtot[q][v];
        int* tbl = g_table + (size_t)((bm0 + q) * PSPL + split) * SS;
        #pragma unroll
        for (int j = 0; j < 8; j++) {
            const unsigned ball = sball[q][w][j];
            const int pre = __popc(ball & lt);
            if (((ball >> lane) & 1u) && (run + pre) < SS)
                tbl[run + pre] = base_local + j * 32 + lane;
            run += __popc(ball);
        }
    }

    if (tid < BPC) {
        int tot = 0;
        #pragma unroll
        for (int v = 0; v < 16; v++) tot += wtot[tid][v];
        g_cnt[(bm0 + tid) * PSPL + split] = tot;
    }
}

// ---------------------------------------------------------------------------
// Kernel 2: gather — direct, phase-specialized float4 stores, no staging.
// One CTA per box, 512 threads. Row s starts at float offset 131*s; with
// h = s&3, (131*s + h) % 4 == 0, so the row is written as h head scalars
// (points), 32 aligned STG.128 (one per lane), and 3-h tail scalars.
// Values come from ONE aligned LDG.128 per lane (frow4[lane]) realigned
// in registers via shfl_up(1) + compile-time selects per phase.
// ---------------------------------------------------------------------------
__global__ __launch_bounds__(512) void roipool_gather_kernel(
    const float* __restrict__ points,   // (B, N, 3)
    const float* __restrict__ feats,    // (B, N, C)
    float* __restrict__ out,            // (B, M, S, 131)
    float* __restrict__ flags)          // (B, M)
{
    const int bm = blockIdx.x;
    const int b  = bm >> 7;             // / MM
    const int tid  = threadIdx.x;
    const int lane = tid & 31;
    const int w    = tid >> 5;          // 0..15

    __shared__ int sidx[SS];
    __shared__ int pf[4];
    __shared__ int scnt;

    if (tid == 0) {
        const int c0 = g_cnt[bm * PSPL + 0];
        const int c1 = g_cnt[bm * PSPL + 1];
        const int c2 = g_cnt[bm * PSPL + 2];
        const int c3 = g_cnt[bm * PSPL + 3];
        pf[0] = 0; pf[1] = c0; pf[2] = c0 + c1; pf[3] = c0 + c1 + c2;
        const int tot = c0 + c1 + c2 + c3;
        scnt = tot;
        flags[bm] = (tot == 0) ? 1.0f : 0.0f;
    }
    __syncthreads();
    const int cnt = scnt;

    float* obox = out + (size_t)bm * SS * OUTF;

    if (cnt == 0) {
        const float4 zz = make_float4(0.f, 0.f, 0.f, 0.f);
        float4* o4 = (float4*)obox;
        for (int i = tid; i < SS * OUTF / 4; i += 512) o4[i] = zz;
        return;
    }

    // resolve wrap-around index for this thread's row (proven logic)
    {
        const int s = tid;                       // SS == blockDim.x
        const int j = s % cnt;
        const int p = (j >= pf[3]) ? 3 : (j >= pf[2]) ? 2 : (j >= pf[1]) ? 1 : 0;
        sidx[s] = g_table[(size_t)(bm * PSPL + p) * SS + (j - pf[p])];
    }
    __syncthreads();

    const float* pbat = points + (size_t)b * NPTS * 3;
    const float* fbat = feats  + (size_t)b * NPTS * CF;
    const unsigned FULL = 0xffffffffu;

    // warp w handles rows 32w .. 32w+31, 4 rows (phases 0..3) per iteration
    const int s0 = w * 32;
    for (int i = 0; i < 8; i++) {
        const int sb = s0 + i * 4;

        // ---- load phase: 4 independent rows in flight ----
        float4 a[4];
        float  pvv[4];
        #pragma unroll
        for (int r = 0; r < 4; r++) {
            const int idx = sidx[sb + r];
            a[r]   = ((const float4*)(fbat + (size_t)idx * CF))[lane];
            pvv[r] = (lane < 3) ? pbat[(size_t)idx * 3 + lane] : 0.0f;
        }

        // ---- compute + store phase (r is compile-time in unrolled body) ----
        #pragma unroll
        for (int r = 0; r < 4; r++) {
            const float p0 = __shfl_sync(FULL, pvv[r], 0);
            const float p1 = __shfl_sync(FULL, pvv[r], 1);
            const float p2 = __shfl_sync(FULL, pvv[r], 2);

            float4 bq;
            if (r == 3) {
                bq = a[r];
            } else {
                const float nx = __shfl_up_sync(FULL, a[r].x, 1);
                const float ny = __shfl_up_sync(FULL, a[r].y, 1);
                const float nz = __shfl_up_sync(FULL, a[r].z, 1);
                const float nw = __shfl_up_sync(FULL, a[r].w, 1);
                (void)nx;
                if (r == 0) bq = make_float4(ny, nz, nw, a[r].x);
                if (r == 1) bq = make_float4(nz, nw, a[r].x, a[r].y);
                if (r == 2) bq = make_float4(nw, a[r].x, a[r].y, a[r].z);
            }
            if (lane == 0) {
                if (r == 0) { bq.x = p0; bq.y = p1; bq.z = p2; }
                if (r == 1) { bq.x = p1; bq.y = p2; }
                if (r == 2) { bq.x = p2; }
            }

            float* orow = obox + (size_t)(sb + r) * OUTF;

            // head scalars: cols 0..r-1 are points
            if (lane < r) orow[lane] = (lane == 0) ? p0 : ((lane == 1) ? p1 : p2);

            // main: 32 aligned float4 stores (offset r + 4*lane, (131s+r)%4==0)
            *(float4*)(orow + r + 4 * lane) = bq;

            // tail scalars: cols r+128..130 = feats[r+125..127] from lane 31's a
            if (r < 3) {
                const float ty = __shfl_sync(FULL, a[r].y, 31);  // feats[125]
                const float tz = __shfl_sync(FULL, a[r].z, 31);  // feats[126]
                const float tw = __shfl_sync(FULL, a[r].w, 31);  // feats[127]
                if (r == 0) { if (lane < 3) orow[128 + lane] = (lane == 0) ? ty : ((lane == 1) ? tz : tw); }
                if (r == 1) { if (lane < 2) orow[129 + lane] = (lane == 0) ? tz : tw; }
                if (r == 2) { if (lane < 1) orow[130] = tw; }
            }
        }
    }
}

// ---------------------------------------------------------------------------
extern "C" void kernel_launch(void* const* d_in, const int* in_sizes, int n_in,
                              void* d_out, int out_size)
{
    const float* points = (const float*)d_in[0];   // (B, N, 3)
    const float* feats  = (const float*)d_in[1];   // (B, N, C)
    const float* boxes  = (const float*)d_in[2];   // (B, M, 7)

    float* out   = (float*)d_out;
    float* flags = out + (size_t)BB * MM * SS * OUTF;  // empty flags appended

    roipool_mask_kernel<<<(BB * MM / BPC) * PSPL, 512>>>(points, boxes);
    roipool_gather_kernel<<<BB * MM, 512>>>(points, feats, out, flags);
}